// round 1
// baseline (speedup 1.0000x reference)
#include <cuda_runtime.h>
#include <math.h>

#define BB   8
#define NN   2048
#define DD   512
#define NEPS 1e-5f

// Scratch (static __device__ globals — allocation-free per harness rules)
__device__ float g_S[(size_t)BB * NN * NN];   // masked, scaled scores (pre-normalization)
__device__ float g_V[(size_t)BB * NN * DD];   // elu(X @ W^T + b)
__device__ float g_rnorm[BB * NN];            // per-row sum of squares of scores

// ---------------------------------------------------------------------------
// Kernel 0: zero the row-norm accumulators
// ---------------------------------------------------------------------------
__global__ void zero_rnorm_kernel() {
    int i = blockIdx.x * blockDim.x + threadIdx.x;
    if (i < BB * NN) g_rnorm[i] = 0.0f;
}

// ---------------------------------------------------------------------------
// Kernel 1: g_V = elu(X @ W^T + bias)   (NT GEMM, M=B*N=16384, N=512, K=512)
// 128x128 tile, BK=8, 256 threads, 8x8 micro-tile
// ---------------------------------------------------------------------------
__global__ __launch_bounds__(256) void vproj_kernel(
    const float* __restrict__ X, const float* __restrict__ W,
    const float* __restrict__ bias)
{
    __shared__ float As[8][128];
    __shared__ float Bs[8][128];
    const int tid     = threadIdx.x;
    const int rowBase = blockIdx.y * 128;     // over M = 16384
    const int colBase = blockIdx.x * 128;     // over E = 512
    const int rowg    = (tid >> 4) * 8;
    const int colg    = (tid & 15) * 8;
    const int lr      = tid >> 1;             // 0..127
    const int lc      = (tid & 1) * 4;        // 0 or 4

    float acc[8][8] = {};

    for (int kb = 0; kb < DD; kb += 8) {
        float4 a = *(const float4*)(X + (size_t)(rowBase + lr) * DD + kb + lc);
        float4 w = *(const float4*)(W + (size_t)(colBase + lr) * DD + kb + lc);
        As[lc + 0][lr] = a.x; As[lc + 1][lr] = a.y;
        As[lc + 2][lr] = a.z; As[lc + 3][lr] = a.w;
        Bs[lc + 0][lr] = w.x; Bs[lc + 1][lr] = w.y;
        Bs[lc + 2][lr] = w.z; Bs[lc + 3][lr] = w.w;
        __syncthreads();
        #pragma unroll
        for (int kk = 0; kk < 8; kk++) {
            float ra[8], rb[8];
            *(float4*)&ra[0] = *(const float4*)&As[kk][rowg];
            *(float4*)&ra[4] = *(const float4*)&As[kk][rowg + 4];
            *(float4*)&rb[0] = *(const float4*)&Bs[kk][colg];
            *(float4*)&rb[4] = *(const float4*)&Bs[kk][colg + 4];
            #pragma unroll
            for (int i = 0; i < 8; i++)
                #pragma unroll
                for (int j = 0; j < 8; j++)
                    acc[i][j] = fmaf(ra[i], rb[j], acc[i][j]);
        }
        __syncthreads();
    }

    #pragma unroll
    for (int i = 0; i < 8; i++) {
        const size_t row = (size_t)(rowBase + rowg + i);
        #pragma unroll
        for (int j = 0; j < 8; j++) {
            const int e = colBase + colg + j;
            float v = acc[i][j] + bias[e];
            v = v > 0.0f ? v : expm1f(v);
            g_V[row * DD + e] = v;
        }
    }
}

// ---------------------------------------------------------------------------
// Kernel 2: g_S = (X/sqrt(D)) @ X^T * mask, accumulate row sum-of-squares
// NT GEMM per batch, M=N=2048, K=512
// ---------------------------------------------------------------------------
__global__ __launch_bounds__(256) void scores_kernel(
    const float* __restrict__ X, const float* __restrict__ mask)
{
    __shared__ float As[8][128];
    __shared__ float Bs[8][128];
    const int b = blockIdx.z;
    const float* Xb = X    + (size_t)b * NN * DD;
    const float* Mb = mask + (size_t)b * NN * NN;
    float*       Sb = g_S  + (size_t)b * NN * NN;

    const int tid   = threadIdx.x;
    const int iBase = blockIdx.y * 128;
    const int jBase = blockIdx.x * 128;
    const int rowg  = (tid >> 4) * 8;
    const int colg  = (tid & 15) * 8;
    const int lr    = tid >> 1;
    const int lc    = (tid & 1) * 4;

    float acc[8][8] = {};

    for (int kb = 0; kb < DD; kb += 8) {
        float4 a = *(const float4*)(Xb + (size_t)(iBase + lr) * DD + kb + lc);
        float4 c = *(const float4*)(Xb + (size_t)(jBase + lr) * DD + kb + lc);
        As[lc + 0][lr] = a.x; As[lc + 1][lr] = a.y;
        As[lc + 2][lr] = a.z; As[lc + 3][lr] = a.w;
        Bs[lc + 0][lr] = c.x; Bs[lc + 1][lr] = c.y;
        Bs[lc + 2][lr] = c.z; Bs[lc + 3][lr] = c.w;
        __syncthreads();
        #pragma unroll
        for (int kk = 0; kk < 8; kk++) {
            float ra[8], rb[8];
            *(float4*)&ra[0] = *(const float4*)&As[kk][rowg];
            *(float4*)&ra[4] = *(const float4*)&As[kk][rowg + 4];
            *(float4*)&rb[0] = *(const float4*)&Bs[kk][colg];
            *(float4*)&rb[4] = *(const float4*)&Bs[kk][colg + 4];
            #pragma unroll
            for (int i = 0; i < 8; i++)
                #pragma unroll
                for (int j = 0; j < 8; j++)
                    acc[i][j] = fmaf(ra[i], rb[j], acc[i][j]);
        }
        __syncthreads();
    }

    const float invt = 0.044194173824159216f;  // 1/sqrt(512)
    float ssq[8];
    #pragma unroll
    for (int i = 0; i < 8; i++) {
        const int gi = iBase + rowg + i;
        const float* mrow = Mb + (size_t)gi * NN + jBase + colg;
        float*       srow = Sb + (size_t)gi * NN + jBase + colg;
        float4 m0 = *(const float4*)(mrow);
        float4 m1 = *(const float4*)(mrow + 4);
        float4 s0, s1;
        s0.x = acc[i][0] * invt * m0.x;
        s0.y = acc[i][1] * invt * m0.y;
        s0.z = acc[i][2] * invt * m0.z;
        s0.w = acc[i][3] * invt * m0.w;
        s1.x = acc[i][4] * invt * m1.x;
        s1.y = acc[i][5] * invt * m1.y;
        s1.z = acc[i][6] * invt * m1.z;
        s1.w = acc[i][7] * invt * m1.w;
        *(float4*)(srow)     = s0;
        *(float4*)(srow + 4) = s1;
        ssq[i] = s0.x * s0.x + s0.y * s0.y + s0.z * s0.z + s0.w * s0.w
               + s1.x * s1.x + s1.y * s1.y + s1.z * s1.z + s1.w * s1.w;
    }

    // reduce across the 16 lanes sharing a row group, then one atomic per row
    #pragma unroll
    for (int i = 0; i < 8; i++) {
        float v = ssq[i];
        #pragma unroll
        for (int off = 8; off > 0; off >>= 1)
            v += __shfl_xor_sync(0xffffffffu, v, off);
        if ((tid & 15) == 0)
            atomicAdd(&g_rnorm[b * NN + iBase + rowg + i], v);
    }
}

// ---------------------------------------------------------------------------
// Kernel 3: out = (g_S / max(||row||, eps)) @ g_V
// NN GEMM per batch, M=2048, N=512, K=2048
// ---------------------------------------------------------------------------
__global__ __launch_bounds__(256) void out_kernel(float* __restrict__ out)
{
    __shared__ float As[8][128];
    __shared__ float Bs[8][128];
    const int b = blockIdx.z;
    const float* Sb = g_S + (size_t)b * NN * NN;
    const float* Vb = g_V + (size_t)b * NN * DD;
    float*       Ob = out + (size_t)b * NN * DD;

    const int tid     = threadIdx.x;
    const int iBase   = blockIdx.y * 128;   // rows i
    const int colBase = blockIdx.x * 128;   // cols e
    const int rowg    = (tid >> 4) * 8;
    const int colg    = (tid & 15) * 8;
    const int lrA     = tid >> 1;
    const int lcA     = (tid & 1) * 4;
    const int lrB     = tid >> 5;           // 0..7
    const int lcB     = (tid & 31) * 4;     // 0..124

    float acc[8][8] = {};

    for (int kb = 0; kb < NN; kb += 8) {
        float4 a = *(const float4*)(Sb + (size_t)(iBase + lrA) * NN + kb + lcA);
        float4 v = *(const float4*)(Vb + (size_t)(kb + lrB) * DD + colBase + lcB);
        As[lcA + 0][lrA] = a.x; As[lcA + 1][lrA] = a.y;
        As[lcA + 2][lrA] = a.z; As[lcA + 3][lrA] = a.w;
        *(float4*)&Bs[lrB][lcB] = v;
        __syncthreads();
        #pragma unroll
        for (int kk = 0; kk < 8; kk++) {
            float ra[8], rb[8];
            *(float4*)&ra[0] = *(const float4*)&As[kk][rowg];
            *(float4*)&ra[4] = *(const float4*)&As[kk][rowg + 4];
            *(float4*)&rb[0] = *(const float4*)&Bs[kk][colg];
            *(float4*)&rb[4] = *(const float4*)&Bs[kk][colg + 4];
            #pragma unroll
            for (int i = 0; i < 8; i++)
                #pragma unroll
                for (int j = 0; j < 8; j++)
                    acc[i][j] = fmaf(ra[i], rb[j], acc[i][j]);
        }
        __syncthreads();
    }

    #pragma unroll
    for (int i = 0; i < 8; i++) {
        const int gi = iBase + rowg + i;
        const float nr  = sqrtf(g_rnorm[b * NN + gi]);
        const float inv = 1.0f / fmaxf(nr, NEPS);
        float* orow = Ob + (size_t)gi * DD + colBase + colg;
        float4 o0, o1;
        o0.x = acc[i][0] * inv; o0.y = acc[i][1] * inv;
        o0.z = acc[i][2] * inv; o0.w = acc[i][3] * inv;
        o1.x = acc[i][4] * inv; o1.y = acc[i][5] * inv;
        o1.z = acc[i][6] * inv; o1.w = acc[i][7] * inv;
        *(float4*)(orow)     = o0;
        *(float4*)(orow + 4) = o1;
    }
}

// ---------------------------------------------------------------------------
extern "C" void kernel_launch(void* const* d_in, const int* in_sizes, int n_in,
                              void* d_out, int out_size)
{
    const float* X    = (const float*)d_in[0];   // output: [8, 2048, 512]
    const float* mask = (const float*)d_in[1];   // slf_attn_mask: [8, 2048, 2048]
    const float* W    = (const float*)d_in[2];   // [512, 512]
    const float* bias = (const float*)d_in[3];   // [512]
    float* out = (float*)d_out;                  // [8, 2048, 512] fp32

    zero_rnorm_kernel<<<(BB * NN + 255) / 256, 256>>>();
    vproj_kernel<<<dim3(DD / 128, (BB * NN) / 128), 256>>>(X, W, bias);
    scores_kernel<<<dim3(NN / 128, NN / 128, BB), 256>>>(X, mask);
    out_kernel<<<dim3(DD / 128, NN / 128, BB), 256>>>(out);
}

// round 3
// speedup vs baseline: 2.4621x; 2.4621x over previous
#include <cuda_runtime.h>
#include <cuda_bf16.h>
#include <math.h>
#include <stdint.h>

#define BB 8
#define NN 2048
#define DD 512
#define MM (BB * NN)
#define NEPS 1e-5f

// Scratch (__device__ globals — allocation-free per harness rules)
__device__ uint16_t g_Shi[(size_t)BB * NN * NN];  // masked scaled scores, bf16 hi
__device__ uint16_t g_Slo[(size_t)BB * NN * NN];  // bf16 lo residual
__device__ uint16_t g_Vhi[(size_t)MM * DD];       // elu(XW^T+b), bf16 hi, [token][e]
__device__ uint16_t g_Vlo[(size_t)MM * DD];
__device__ float    g_rnorm[MM];                  // per-row sum of squares of S

// ---------------------------------------------------------------------------
// helpers
// ---------------------------------------------------------------------------
__device__ __forceinline__ uint32_t smem_u32(const void* p) {
    uint32_t a;
    asm("{ .reg .u64 t; cvta.to.shared.u64 t, %1; cvt.u32.u64 %0, t; }"
        : "=r"(a) : "l"(p));
    return a;
}

__device__ __forceinline__ void ldsm_x4(uint32_t* r, uint32_t a) {
    asm volatile("ldmatrix.sync.aligned.m8n8.x4.shared.b16 {%0,%1,%2,%3}, [%4];"
                 : "=r"(r[0]), "=r"(r[1]), "=r"(r[2]), "=r"(r[3]) : "r"(a));
}
__device__ __forceinline__ void ldsm_x4t(uint32_t* r, uint32_t a) {
    asm volatile("ldmatrix.sync.aligned.m8n8.x4.trans.shared.b16 {%0,%1,%2,%3}, [%4];"
                 : "=r"(r[0]), "=r"(r[1]), "=r"(r[2]), "=r"(r[3]) : "r"(a));
}
__device__ __forceinline__ void mma16816(float* d, const uint32_t* a, const uint32_t* b) {
    asm volatile(
        "mma.sync.aligned.m16n8k16.row.col.f32.bf16.bf16.f32 "
        "{%0,%1,%2,%3}, {%4,%5,%6,%7}, {%8,%9}, {%0,%1,%2,%3};"
        : "+f"(d[0]), "+f"(d[1]), "+f"(d[2]), "+f"(d[3])
        : "r"(a[0]), "r"(a[1]), "r"(a[2]), "r"(a[3]), "r"(b[0]), "r"(b[1]));
}

// pack two fp32 -> bf16x2 hi, plus bf16x2 residual lo
__device__ __forceinline__ uint32_t packsplit(float x0, float x1, uint32_t& lo) {
    uint32_t h;
    asm("cvt.rn.bf16x2.f32 %0, %1, %2;" : "=r"(h) : "f"(x1), "f"(x0));
    float r0 = x0 - __uint_as_float(h << 16);
    float r1 = x1 - __uint_as_float(h & 0xffff0000u);
    asm("cvt.rn.bf16x2.f32 %0, %1, %2;" : "=r"(lo) : "f"(r1), "f"(r0));
    return h;
}

__device__ __forceinline__ void split4(float4 x, uint2& hi, uint2& lo) {
    uint32_t l0, l1;
    uint32_t h0 = packsplit(x.x, x.y, l0);
    uint32_t h1 = packsplit(x.z, x.w, l1);
    hi = make_uint2(h0, h1);
    lo = make_uint2(l0, l1);
}

// ---------------------------------------------------------------------------
// compute one K=32 chunk: acc[2][8][4] += A(128x32) * B^T, bf16x3 products
// SMEM layout at stage base sb (shared addr):
//   A hi @ 0 (pitch 80), A lo @ 10240, B hi @ 20480 (pitch BP), B lo @ BLO
// ---------------------------------------------------------------------------
template <bool BT, int BLO, int BP>
__device__ __forceinline__ void compute_chunk(uint32_t sb, int wm, int wn, int lane,
                                              float acc[2][8][4]) {
    #pragma unroll
    for (int s = 0; s < 2; s++) {
        uint32_t Ah[2][4], Al[2][4], Bh[8][2], Bl[8][2];
        uint32_t aaddr = sb + (uint32_t)((wm * 32 + (lane & 15)) * 80
                                         + (s * 16 + (lane >> 4) * 8) * 2);
        ldsm_x4(Ah[0], aaddr);
        ldsm_x4(Ah[1], aaddr + 16 * 80);
        ldsm_x4(Al[0], aaddr + 10240);
        ldsm_x4(Al[1], aaddr + 10240 + 16 * 80);

        #pragma unroll
        for (int p = 0; p < 4; p++) {
            uint32_t r[4], baddr;
            if (!BT) {
                int n  = wn * 64 + p * 16 + (lane >> 4) * 8 + (lane & 7);
                int kc = s * 16 + ((lane >> 3) & 1) * 8;
                baddr = sb + 20480u + (uint32_t)(n * BP + kc * 2);
                ldsm_x4(r, baddr);
                Bh[2*p][0] = r[0]; Bh[2*p][1] = r[1];
                Bh[2*p+1][0] = r[2]; Bh[2*p+1][1] = r[3];
                ldsm_x4(r, baddr + (uint32_t)(BLO - 20480));
                Bl[2*p][0] = r[0]; Bl[2*p][1] = r[1];
                Bl[2*p+1][0] = r[2]; Bl[2*p+1][1] = r[3];
            } else {
                int k = s * 16 + (lane & 7) + ((lane >> 3) & 1) * 8;
                int n = wn * 64 + p * 16 + (lane >> 4) * 8;
                baddr = sb + 20480u + (uint32_t)(k * BP + n * 2);
                ldsm_x4t(r, baddr);
                Bh[2*p][0] = r[0]; Bh[2*p][1] = r[1];
                Bh[2*p+1][0] = r[2]; Bh[2*p+1][1] = r[3];
                ldsm_x4t(r, baddr + (uint32_t)(BLO - 20480));
                Bl[2*p][0] = r[0]; Bl[2*p][1] = r[1];
                Bl[2*p+1][0] = r[2]; Bl[2*p+1][1] = r[3];
            }
        }
        #pragma unroll
        for (int mf = 0; mf < 2; mf++)
            #pragma unroll
            for (int nf = 0; nf < 8; nf++) {
                mma16816(acc[mf][nf], Ah[mf], Bh[nf]);
                mma16816(acc[mf][nf], Ah[mf], Bl[nf]);
                mma16816(acc[mf][nf], Al[mf], Bh[nf]);
            }
    }
}

// ---------------------------------------------------------------------------
// fp32 tile staging (scores / vproj): A[128][32], B[128][32] -> hi/lo bf16
// ---------------------------------------------------------------------------
struct F4x8 { float4 v[8]; };

__device__ __forceinline__ void ldg_f32(F4x8& rg, const float* __restrict__ A, size_t lda,
                                        const float* __restrict__ Bm, size_t ldb,
                                        int kc, int tid) {
    int r = tid >> 1, h = tid & 1;
    const float* pa = A  + (size_t)r * lda + kc + h * 16;
    const float* pb = Bm + (size_t)r * ldb + kc + h * 16;
    #pragma unroll
    for (int q = 0; q < 4; q++) {
        rg.v[q]     = *(const float4*)(pa + q * 4);
        rg.v[4 + q] = *(const float4*)(pb + q * 4);
    }
}

__device__ __forceinline__ void sts_f32(const F4x8& rg, uint8_t* st, int tid) {
    int r = tid >> 1, h = tid & 1;
    uint8_t* pa = st + r * 80 + h * 32;
    uint8_t* pb = pa + 20480;
    #pragma unroll
    for (int q = 0; q < 4; q++) {
        uint2 hi, lo;
        split4(rg.v[q], hi, lo);
        *(uint2*)(pa + q * 8)         = hi;
        *(uint2*)(pa + 10240 + q * 8) = lo;
        split4(rg.v[4 + q], hi, lo);
        *(uint2*)(pb + q * 8)         = hi;
        *(uint2*)(pb + 10240 + q * 8) = lo;
    }
}

// ---------------------------------------------------------------------------
// bf16 tile staging (out): S[128][32] (pitch 80) + V[32][128] (pitch 272)
// ---------------------------------------------------------------------------
struct U4x8 { uint4 v[8]; };

__device__ __forceinline__ void ldg_bf(U4x8& rg,
                                       const uint16_t* __restrict__ Shi,
                                       const uint16_t* __restrict__ Slo,
                                       const uint16_t* __restrict__ Vhi,
                                       const uint16_t* __restrict__ Vlo,
                                       int eBase, int kc, int tid) {
    int r = tid >> 1, h = tid & 1;
    const uint16_t* ps = Shi + (size_t)r * NN + kc + h * 16;
    const uint16_t* pl = Slo + (size_t)r * NN + kc + h * 16;
    rg.v[0] = *(const uint4*)ps;       rg.v[1] = *(const uint4*)(ps + 8);
    rg.v[2] = *(const uint4*)pl;       rg.v[3] = *(const uint4*)(pl + 8);
    int kr = tid >> 3, sg = tid & 7;
    const uint16_t* pv  = Vhi + (size_t)(kc + kr) * DD + eBase + sg * 16;
    const uint16_t* pvl = Vlo + (size_t)(kc + kr) * DD + eBase + sg * 16;
    rg.v[4] = *(const uint4*)pv;       rg.v[5] = *(const uint4*)(pv + 8);
    rg.v[6] = *(const uint4*)pvl;      rg.v[7] = *(const uint4*)(pvl + 8);
}

__device__ __forceinline__ void sts_bf(const U4x8& rg, uint8_t* st, int tid) {
    int r = tid >> 1, h = tid & 1;
    uint8_t* pa = st + r * 80 + h * 32;
    *(uint4*)(pa)              = rg.v[0];
    *(uint4*)(pa + 16)         = rg.v[1];
    *(uint4*)(pa + 10240)      = rg.v[2];
    *(uint4*)(pa + 10240 + 16) = rg.v[3];
    int kr = tid >> 3, sg = tid & 7;
    uint8_t* pv = st + 20480 + kr * 272 + sg * 32;
    *(uint4*)(pv)             = rg.v[4];
    *(uint4*)(pv + 16)        = rg.v[5];
    *(uint4*)(pv + 8704)      = rg.v[6];
    *(uint4*)(pv + 8704 + 16) = rg.v[7];
}

#define STRIDE_F 40960
#define STRIDE_O 37888

// ---------------------------------------------------------------------------
// Kernel: zero rnorm
// ---------------------------------------------------------------------------
__global__ void zero_rnorm_kernel() {
    int i = blockIdx.x * blockDim.x + threadIdx.x;
    if (i < MM) g_rnorm[i] = 0.0f;
}

// ---------------------------------------------------------------------------
// Kernel 1: V = elu(X @ W^T + b) -> g_Vhi/g_Vlo [token][e]
// grid (4, 128)
// ---------------------------------------------------------------------------
__global__ __launch_bounds__(256, 1)
void vproj_kernel(const float* __restrict__ X, const float* __restrict__ W,
                  const float* __restrict__ bias) {
    extern __shared__ __align__(16) uint8_t smem[];
    const int tid = threadIdx.x, wid = tid >> 5, lane = tid & 31;
    const int wm = wid & 3, wn = wid >> 2;
    const int eBase = blockIdx.x * 128, mBase = blockIdx.y * 128;
    const float* A0 = X + (size_t)mBase * DD;
    const float* B0 = W + (size_t)eBase * DD;
    uint32_t sb = smem_u32(smem);

    float acc[2][8][4] = {};
    F4x8 rg;
    ldg_f32(rg, A0, DD, B0, DD, 0, tid);
    sts_f32(rg, smem, tid);
    __syncthreads();
    for (int c = 0; c < 16; c++) {
        if (c + 1 < 16) ldg_f32(rg, A0, DD, B0, DD, (c + 1) * 32, tid);
        compute_chunk<false, 30720, 80>(sb + (c & 1) * STRIDE_F, wm, wn, lane, acc);
        if (c + 1 < 16) {
            sts_f32(rg, smem + ((c + 1) & 1) * STRIDE_F, tid);
            __syncthreads();
        }
    }

    const int l4 = lane >> 2, lm = lane & 3;
    #pragma unroll
    for (int mf = 0; mf < 2; mf++) {
        const int r0 = mBase + wm * 32 + mf * 16 + l4;
        #pragma unroll
        for (int nf = 0; nf < 8; nf++) {
            const int e = eBase + wn * 64 + nf * 8 + lm * 2;
            float2 bv = *(const float2*)(bias + e);
            float v0 = acc[mf][nf][0] + bv.x;
            float v1 = acc[mf][nf][1] + bv.y;
            float v2 = acc[mf][nf][2] + bv.x;
            float v3 = acc[mf][nf][3] + bv.y;
            v0 = v0 > 0.0f ? v0 : expm1f(v0);
            v1 = v1 > 0.0f ? v1 : expm1f(v1);
            v2 = v2 > 0.0f ? v2 : expm1f(v2);
            v3 = v3 > 0.0f ? v3 : expm1f(v3);
            uint32_t lo, hi;
            hi = packsplit(v0, v1, lo);
            *(uint32_t*)(g_Vhi + (size_t)r0 * DD + e) = hi;
            *(uint32_t*)(g_Vlo + (size_t)r0 * DD + e) = lo;
            hi = packsplit(v2, v3, lo);
            *(uint32_t*)(g_Vhi + (size_t)(r0 + 8) * DD + e) = hi;
            *(uint32_t*)(g_Vlo + (size_t)(r0 + 8) * DD + e) = lo;
        }
    }
}

// ---------------------------------------------------------------------------
// Kernel 2: S = (X X^T / sqrt(D)) * mask -> g_Shi/g_Slo, + row ssq atomics
// grid (16, 16, 8)
// ---------------------------------------------------------------------------
__global__ __launch_bounds__(256, 1)
void scores_kernel(const float* __restrict__ X, const float* __restrict__ mask) {
    extern __shared__ __align__(16) uint8_t smem[];
    const int tid = threadIdx.x, wid = tid >> 5, lane = tid & 31;
    const int wm = wid & 3, wn = wid >> 2;
    const int b = blockIdx.z;
    const int iBase = blockIdx.y * 128, jBase = blockIdx.x * 128;
    const float* Xb = X + (size_t)b * NN * DD;
    const float* Mb = mask + (size_t)b * NN * NN;
    uint16_t* Sh = g_Shi + (size_t)b * NN * NN;
    uint16_t* Sl = g_Slo + (size_t)b * NN * NN;
    uint32_t sb = smem_u32(smem);

    const float* A0 = Xb + (size_t)iBase * DD;
    const float* B0 = Xb + (size_t)jBase * DD;

    float acc[2][8][4] = {};
    F4x8 rg;
    ldg_f32(rg, A0, DD, B0, DD, 0, tid);
    sts_f32(rg, smem, tid);
    __syncthreads();
    for (int c = 0; c < 16; c++) {
        if (c + 1 < 16) ldg_f32(rg, A0, DD, B0, DD, (c + 1) * 32, tid);
        compute_chunk<false, 30720, 80>(sb + (c & 1) * STRIDE_F, wm, wn, lane, acc);
        if (c + 1 < 16) {
            sts_f32(rg, smem + ((c + 1) & 1) * STRIDE_F, tid);
            __syncthreads();
        }
    }

    const float invt = 0.044194173824159216f;  // 1/sqrt(512)
    const int l4 = lane >> 2, lm = lane & 3;
    #pragma unroll
    for (int mf = 0; mf < 2; mf++) {
        const int r0 = iBase + wm * 32 + mf * 16 + l4;
        float ss0 = 0.0f, ss8 = 0.0f;
        #pragma unroll
        for (int nf = 0; nf < 8; nf++) {
            const int cc = jBase + wn * 64 + nf * 8 + lm * 2;
            float2 m0 = *(const float2*)(Mb + (size_t)r0 * NN + cc);
            float2 m8 = *(const float2*)(Mb + (size_t)(r0 + 8) * NN + cc);
            float s0 = acc[mf][nf][0] * invt * m0.x;
            float s1 = acc[mf][nf][1] * invt * m0.y;
            float s2 = acc[mf][nf][2] * invt * m8.x;
            float s3 = acc[mf][nf][3] * invt * m8.y;
            ss0 += s0 * s0 + s1 * s1;
            ss8 += s2 * s2 + s3 * s3;
            uint32_t lo, hi;
            hi = packsplit(s0, s1, lo);
            *(uint32_t*)(Sh + (size_t)r0 * NN + cc) = hi;
            *(uint32_t*)(Sl + (size_t)r0 * NN + cc) = lo;
            hi = packsplit(s2, s3, lo);
            *(uint32_t*)(Sh + (size_t)(r0 + 8) * NN + cc) = hi;
            *(uint32_t*)(Sl + (size_t)(r0 + 8) * NN + cc) = lo;
        }
        ss0 += __shfl_xor_sync(0xffffffffu, ss0, 1);
        ss0 += __shfl_xor_sync(0xffffffffu, ss0, 2);
        ss8 += __shfl_xor_sync(0xffffffffu, ss8, 1);
        ss8 += __shfl_xor_sync(0xffffffffu, ss8, 2);
        if (lm == 0) {
            atomicAdd(&g_rnorm[b * NN + r0], ss0);
            atomicAdd(&g_rnorm[b * NN + r0 + 8], ss8);
        }
    }
}

// ---------------------------------------------------------------------------
// Kernel 3: out = diag(1/max(||S row||,eps)) * (S @ V)
// grid (4, 16, 8)
// ---------------------------------------------------------------------------
__global__ __launch_bounds__(256, 1)
void out_kernel(float* __restrict__ out) {
    extern __shared__ __align__(16) uint8_t smem[];
    const int tid = threadIdx.x, wid = tid >> 5, lane = tid & 31;
    const int wm = wid & 3, wn = wid >> 2;
    const int b = blockIdx.z;
    const int iBase = blockIdx.y * 128, eBase = blockIdx.x * 128;
    const uint16_t* Sh = g_Shi + (size_t)b * NN * NN + (size_t)iBase * NN;
    const uint16_t* Sl = g_Slo + (size_t)b * NN * NN + (size_t)iBase * NN;
    const uint16_t* Vh = g_Vhi + (size_t)b * NN * DD;
    const uint16_t* Vl = g_Vlo + (size_t)b * NN * DD;
    uint32_t sb = smem_u32(smem);

    float acc[2][8][4] = {};
    U4x8 rg;
    ldg_bf(rg, Sh, Sl, Vh, Vl, eBase, 0, tid);
    sts_bf(rg, smem, tid);
    __syncthreads();
    for (int c = 0; c < 64; c++) {
        if (c + 1 < 64) ldg_bf(rg, Sh, Sl, Vh, Vl, eBase, (c + 1) * 32, tid);
        compute_chunk<true, 29184, 272>(sb + (c & 1) * STRIDE_O, wm, wn, lane, acc);
        if (c + 1 < 64) {
            sts_bf(rg, smem + ((c + 1) & 1) * STRIDE_O, tid);
            __syncthreads();
        }
    }

    const int l4 = lane >> 2, lm = lane & 3;
    #pragma unroll
    for (int mf = 0; mf < 2; mf++) {
        const int r0 = iBase + wm * 32 + mf * 16 + l4;
        const float inv0 = 1.0f / fmaxf(sqrtf(g_rnorm[b * NN + r0]), NEPS);
        const float inv8 = 1.0f / fmaxf(sqrtf(g_rnorm[b * NN + r0 + 8]), NEPS);
        #pragma unroll
        for (int nf = 0; nf < 8; nf++) {
            const int e = eBase + wn * 64 + nf * 8 + lm * 2;
            float* p0 = out + ((size_t)b * NN + r0) * DD + e;
            float* p8 = out + ((size_t)b * NN + r0 + 8) * DD + e;
            *(float2*)p0 = make_float2(acc[mf][nf][0] * inv0, acc[mf][nf][1] * inv0);
            *(float2*)p8 = make_float2(acc[mf][nf][2] * inv8, acc[mf][nf][3] * inv8);
        }
    }
}

// ---------------------------------------------------------------------------
extern "C" void kernel_launch(void* const* d_in, const int* in_sizes, int n_in,
                              void* d_out, int out_size) {
    const float* X    = (const float*)d_in[0];
    const float* mask = (const float*)d_in[1];
    const float* W    = (const float*)d_in[2];
    const float* bias = (const float*)d_in[3];
    float* out = (float*)d_out;

    static int attr_done = 0;
    if (!attr_done) {
        cudaFuncSetAttribute(vproj_kernel,  cudaFuncAttributeMaxDynamicSharedMemorySize, 2 * STRIDE_F);
        cudaFuncSetAttribute(scores_kernel, cudaFuncAttributeMaxDynamicSharedMemorySize, 2 * STRIDE_F);
        cudaFuncSetAttribute(out_kernel,    cudaFuncAttributeMaxDynamicSharedMemorySize, 2 * STRIDE_O);
        attr_done = 1;
    }

    zero_rnorm_kernel<<<(MM + 255) / 256, 256>>>();
    vproj_kernel<<<dim3(4, 128), 256, 2 * STRIDE_F>>>(X, W, bias);
    scores_kernel<<<dim3(16, 16, 8), 256, 2 * STRIDE_F>>>(X, mask);
    out_kernel<<<dim3(4, 16, 8), 256, 2 * STRIDE_O>>>(out);
}